// round 6
// baseline (speedup 1.0000x reference)
#include <cuda_runtime.h>

// SubdivideMeshes: 3x GCNConv (3->16->16->3) + leaky_relu, vertex offsets,
// edge midpoints, faces broadcast. Fixed dataset shapes:
constexpr int VN = 100000;          // vertices per mesh
constexpr int EN = 300000;          // edges per mesh
constexpr int BN = 16;              // batch
constexpr int NN = BN * VN;         // 1,600,000 batched nodes
constexpr float NEG = 0.01f;

// Scratch (static __device__ arrays: allocation-free per harness rules)
__device__ int   g_cnt[VN];         // in-degree counts (excl. self-loop)
__device__ int   g_rs [VN + 1];     // CSR row starts (by dst)
__device__ int   g_cur[VN];         // fill cursors
__device__ int   g_col[EN];         // CSR: src per in-edge
__device__ float g_val[EN];         // CSR: norm per in-edge
__device__ float g_dinv[VN];        // rsqrt(deg), deg = 1 + in-count
__device__ float g_h  [NN * 16];    // 102.4 MB  (layer inputs h = xW)
__device__ float g_out[NN * 16];    // 102.4 MB  (layer outputs)
__device__ float g_h3 [NN * 3];     // 19.2 MB

// ==================== CSR build (base graph, batch-invariant) ==============
__global__ void k_zero_cnt() {
    int v = blockIdx.x * blockDim.x + threadIdx.x;
    if (v < VN) g_cnt[v] = 0;
}
__global__ void k_count(const int* __restrict__ edges) {
    int e = blockIdx.x * blockDim.x + threadIdx.x;
    if (e < EN) atomicAdd(&g_cnt[edges[2 * e + 1]], 1);
}
// Single-block exclusive scan over VN counts; also emits cursors and dinv.
__global__ void k_scan() {
    __shared__ int sh[1024];
    const int T = 1024, C = (VN + T - 1) / T;   // 98 per thread
    int t = threadIdx.x;
    int beg = t * C, end = min(beg + C, VN);
    int s = 0;
    for (int i = beg; i < end; i++) s += g_cnt[i];
    sh[t] = s;
    __syncthreads();
    for (int off = 1; off < T; off <<= 1) {
        int v = (t >= off) ? sh[t - off] : 0;
        __syncthreads();
        sh[t] += v;
        __syncthreads();
    }
    int run = sh[t] - s;                        // exclusive prefix
    for (int i = beg; i < end; i++) {
        int c = g_cnt[i];
        g_rs[i] = run;
        g_cur[i] = run;
        g_dinv[i] = rsqrtf((float)(1 + c));
        run += c;
    }
    if (t == T - 1) g_rs[VN] = run;
}
__global__ void k_fill(const int* __restrict__ edges) {
    int e = blockIdx.x * blockDim.x + threadIdx.x;
    if (e >= EN) return;
    int s = edges[2 * e];
    int d = edges[2 * e + 1];
    int pos = atomicAdd(&g_cur[d], 1);
    g_col[pos] = s;
    g_val[pos] = g_dinv[s] * g_dinv[d];
}

// ==================== per-node dense transform: h = act(x) @ W =============
template <int FIN, int FOUT, bool LK>
__global__ void k_transform(const float* __restrict__ x,
                            const float* __restrict__ W,
                            float* __restrict__ h) {
    int i = blockIdx.x * blockDim.x + threadIdx.x;
    if (i >= NN) return;
    float xi[FIN];
#pragma unroll
    for (int k = 0; k < FIN; k++) {
        float v = x[(long long)i * FIN + k];
        if (LK) v = v > 0.0f ? v : NEG * v;
        xi[k] = v;
    }
#pragma unroll
    for (int j = 0; j < FOUT; j++) {
        float acc = 0.0f;
#pragma unroll
        for (int k = 0; k < FIN; k++)
            acc = fmaf(xi[k], __ldg(&W[k * FOUT + j]), acc);
        h[(long long)i * FOUT + j] = acc;
    }
}

// ==================== CSR gather, F=16 =====================================
// thread = (node, quad). out[n,:] = h[n,:]/deg + sum_in norm*h[src,:] + bias
// Neighbor loop 2-way unrolled: both gathers in flight before dependent FMAs
// (MLP=2 on the L2-latency-exposed h4 loads).
__global__ void k_gather16(const float* __restrict__ h,
                           const float* __restrict__ bias,
                           float* __restrict__ out) {
    long long t = (long long)blockIdx.x * blockDim.x + threadIdx.x;
    if (t >= (long long)NN * 4) return;
    int q = (int)(t & 3);
    int n = (int)(t >> 2);
    int v = n % VN;
    int b = n / VN;
    float dv = __ldg(&g_dinv[v]);
    float idg = dv * dv;
    const float4* h4 = (const float4*)h;
    long long self = ((long long)n << 2) + q;   // float4 index of h[n] quad q
    float4 hv = h4[self];
    float4 bb = ((const float4*)bias)[q];
    float4 acc;
    acc.x = fmaf(hv.x, idg, bb.x);
    acc.y = fmaf(hv.y, idg, bb.y);
    acc.z = fmaf(hv.z, idg, bb.z);
    acc.w = fmaf(hv.w, idg, bb.w);
    int r0 = __ldg(&g_rs[v]), r1 = __ldg(&g_rs[v + 1]);
    long long bbase = (long long)b * VN;
    int i = r0;
    for (; i + 2 <= r1; i += 2) {
        int   s0 = __ldg(&g_col[i]);
        int   s1 = __ldg(&g_col[i + 1]);
        float w0 = __ldg(&g_val[i]);
        float w1 = __ldg(&g_val[i + 1]);
        float4 ha = h4[((bbase + s0) << 2) + q];
        float4 hb = h4[((bbase + s1) << 2) + q];
        acc.x = fmaf(w0, ha.x, acc.x);
        acc.y = fmaf(w0, ha.y, acc.y);
        acc.z = fmaf(w0, ha.z, acc.z);
        acc.w = fmaf(w0, ha.w, acc.w);
        acc.x = fmaf(w1, hb.x, acc.x);
        acc.y = fmaf(w1, hb.y, acc.y);
        acc.z = fmaf(w1, hb.z, acc.z);
        acc.w = fmaf(w1, hb.w, acc.w);
    }
    if (i < r1) {
        int s = __ldg(&g_col[i]);
        float w = __ldg(&g_val[i]);
        float4 hs = h4[((bbase + s) << 2) + q];
        acc.x = fmaf(w, hs.x, acc.x);
        acc.y = fmaf(w, hs.y, acc.y);
        acc.z = fmaf(w, hs.z, acc.z);
        acc.w = fmaf(w, hs.w, acc.w);
    }
    ((float4*)out)[self] = acc;
}

// ==================== CSR gather, F=3, fused with vertex output ============
// Writes new_verts vert block directly: dout[b,(v),:] = verts[n,:] + gcn3(n,:)
__global__ void k_gather3_vout(const float* __restrict__ h3,
                               const float* __restrict__ bias,
                               const float* __restrict__ verts,
                               float* __restrict__ dout) {
    int n = blockIdx.x * blockDim.x + threadIdx.x;
    if (n >= NN) return;
    int v = n % VN;
    int b = n / VN;
    float dv = __ldg(&g_dinv[v]);
    float idg = dv * dv;
    long long sb = (long long)n * 3;
    float a0 = fmaf(h3[sb + 0], idg, __ldg(&bias[0]));
    float a1 = fmaf(h3[sb + 1], idg, __ldg(&bias[1]));
    float a2 = fmaf(h3[sb + 2], idg, __ldg(&bias[2]));
    int r0 = __ldg(&g_rs[v]), r1 = __ldg(&g_rs[v + 1]);
    long long bbase = (long long)b * VN;
    for (int i = r0; i < r1; i++) {
        int s = __ldg(&g_col[i]);
        float w = __ldg(&g_val[i]);
        long long ss = (bbase + s) * 3;
        a0 = fmaf(w, h3[ss + 0], a0);
        a1 = fmaf(w, h3[ss + 1], a1);
        a2 = fmaf(w, h3[ss + 2], a2);
    }
    long long ob = (long long)b * (VN + EN) * 3 + (long long)v * 3;
    dout[ob + 0] = verts[sb + 0] + a0;
    dout[ob + 1] = verts[sb + 1] + a1;
    dout[ob + 2] = verts[sb + 2] + a2;
}

// ==================== midpoints + faces ====================================
__global__ void k_mid(const int* __restrict__ edges, float* dout) {
    int t = blockIdx.x * blockDim.x + threadIdx.x;
    if (t >= BN * EN) return;
    int e = t % EN;
    int b = t / EN;
    int s = __ldg(&edges[2 * e]);
    int d = __ldg(&edges[2 * e + 1]);
    long long base = (long long)b * (VN + EN) * 3;
#pragma unroll
    for (int k = 0; k < 3; k++)
        dout[base + (long long)(VN + e) * 3 + k] =
            0.5f * (dout[base + (long long)s * 3 + k] +
                    dout[base + (long long)d * 3 + k]);
}

// faces: int -> float broadcast, vectorized x4 (used when fs3 % 4 == 0; the
// dout base offset BN*(VN+EN)*3 = 19.2M floats is a multiple of 4).
__global__ void k_faces4(const int* __restrict__ faces, float* __restrict__ dout,
                         int fs3) {
    int t = blockIdx.x * blockDim.x + threadIdx.x;      // quad index
    int total4 = BN * (fs3 / 4);
    if (t >= total4) return;
    int q = (t * 4) % fs3;                              // multiple of 4
    int4 f = *reinterpret_cast<const int4*>(faces + q);
    float4 o = make_float4((float)f.x, (float)f.y, (float)f.z, (float)f.w);
    reinterpret_cast<float4*>(dout + (long long)BN * (VN + EN) * 3)[t] = o;
}

// scalar fallback for fs3 not divisible by 4 (shape-variant safety)
__global__ void k_faces1(const int* __restrict__ faces, float* __restrict__ dout,
                         int fs3) {
    int t = blockIdx.x * blockDim.x + threadIdx.x;
    if (t >= BN * fs3) return;
    dout[(long long)BN * (VN + EN) * 3 + t] = (float)faces[t % fs3];
}

// ==================== host =================================================
static inline unsigned gdim(long long n) { return (unsigned)((n + 255) / 256); }

extern "C" void kernel_launch(void* const* d_in, const int* in_sizes, int n_in,
                              void* d_out, int out_size) {
    const float* verts = (const float*)d_in[0];
    const int*   edges = (const int*)  d_in[1];
    const int*   faces = (const int*)  d_in[2];
    const float* W1 = (const float*)d_in[3];
    const float* b1 = (const float*)d_in[4];
    const float* W2 = (const float*)d_in[5];
    const float* b2 = (const float*)d_in[6];
    const float* W3 = (const float*)d_in[7];
    const float* b3 = (const float*)d_in[8];
    int fs3 = in_sizes[2];                 // Fsub*3
    float* out = (float*)d_out;

    float *p_h, *p_out, *p_h3;
    cudaGetSymbolAddress((void**)&p_h,   g_h);
    cudaGetSymbolAddress((void**)&p_out, g_out);
    cudaGetSymbolAddress((void**)&p_h3,  g_h3);

    const int T = 256;

    // CSR build (base graph)
    k_zero_cnt<<<gdim(VN), T>>>();
    k_count   <<<gdim(EN), T>>>(edges);
    k_scan    <<<1, 1024>>>();
    k_fill    <<<gdim(EN), T>>>(edges);

    // layer 1: 3 -> 16
    k_transform<3, 16, false><<<gdim(NN), T>>>(verts, W1, p_h);
    k_gather16<<<gdim((long long)NN * 4), T>>>(p_h, b1, p_out);

    // layer 2: 16 -> 16
    k_transform<16, 16, true><<<gdim(NN), T>>>(p_out, W2, p_h);
    k_gather16<<<gdim((long long)NN * 4), T>>>(p_h, b2, p_out);

    // layer 3: 16 -> 3, fused with vertex output (verts + offs -> dout)
    k_transform<16, 3, true><<<gdim(NN), T>>>(p_out, W3, p_h3);
    k_gather3_vout<<<gdim(NN), T>>>(p_h3, b3, verts, out);

    // midpoints + faces
    k_mid<<<gdim((long long)BN * EN), T>>>(edges, out);
    if ((fs3 & 3) == 0)
        k_faces4<<<gdim((long long)BN * (fs3 / 4)), T>>>(faces, out, fs3);
    else
        k_faces1<<<gdim((long long)BN * fs3), T>>>(faces, out, fs3);
}

// round 7
// speedup vs baseline: 1.4630x; 1.4630x over previous
#include <cuda_runtime.h>

// SubdivideMeshes: 3x GCNConv (3->16->16->3) + leaky_relu, vertex offsets,
// edge midpoints, faces broadcast. Fixed dataset shapes:
constexpr int VN = 100000;          // vertices per mesh
constexpr int EN = 300000;          // edges per mesh
constexpr int BN = 16;              // batch
constexpr int NN = BN * VN;         // 1,600,000 batched nodes
constexpr float NEG = 0.01f;

// Key identity: GCN out = Ahat(xW)+b = (Ahat x)W + b  (Ahat has diagonal
// normalization, commutes with right-multiplication). We aggregate in the
// NARROW dim per layer: L1 agg in 3-dim -> W1 epilogue; L2 agg in 16-dim ->
// W2+W3 fused epilogue (only h3 = y2*W3 is ever needed); L3 agg in 3-dim.

// Scratch (static __device__ arrays: allocation-free per harness rules)
__device__ int   g_cnt[VN];         // in-degree counts (excl. self-loop)
__device__ int   g_rs [VN + 1];     // CSR row starts (by dst)
__device__ int   g_cur[VN];         // fill cursors
__device__ int   g_col[EN];         // CSR: src per in-edge
__device__ float g_val[EN];         // CSR: norm per in-edge
__device__ float g_dinv[VN];        // rsqrt(deg), deg = 1 + in-count
__device__ float g_y1 [NN * 16];    // 102.4 MB  (layer-1 output, leaky applied)
__device__ float g_h3 [NN * 3];     // 19.2 MB   (y2 @ W3, pre-aggregation)

// ==================== CSR build (base graph, batch-invariant) ==============
__global__ void k_zero_cnt() {
    int v = blockIdx.x * blockDim.x + threadIdx.x;
    if (v < VN) g_cnt[v] = 0;
}
__global__ void k_count(const int* __restrict__ edges) {
    int e = blockIdx.x * blockDim.x + threadIdx.x;
    if (e < EN) atomicAdd(&g_cnt[edges[2 * e + 1]], 1);
}
// Single-block exclusive scan over VN counts; also emits cursors and dinv.
__global__ void k_scan() {
    __shared__ int sh[1024];
    const int T = 1024, C = (VN + T - 1) / T;
    int t = threadIdx.x;
    int beg = t * C, end = min(beg + C, VN);
    int s = 0;
    for (int i = beg; i < end; i++) s += g_cnt[i];
    sh[t] = s;
    __syncthreads();
    for (int off = 1; off < T; off <<= 1) {
        int v = (t >= off) ? sh[t - off] : 0;
        __syncthreads();
        sh[t] += v;
        __syncthreads();
    }
    int run = sh[t] - s;
    for (int i = beg; i < end; i++) {
        int c = g_cnt[i];
        g_rs[i] = run;
        g_cur[i] = run;
        g_dinv[i] = rsqrtf((float)(1 + c));
        run += c;
    }
    if (t == T - 1) g_rs[VN] = run;
}
__global__ void k_fill(const int* __restrict__ edges) {
    int e = blockIdx.x * blockDim.x + threadIdx.x;
    if (e >= EN) return;
    int s = edges[2 * e];
    int d = edges[2 * e + 1];
    int pos = atomicAdd(&g_cur[d], 1);
    g_col[pos] = s;
    g_val[pos] = g_dinv[s] * g_dinv[d];
}

// Generic 3-dim aggregation helper: a[0..2] = Ahat-weighted sum over row v
// of x (batched node base bbase), self term included.
__device__ __forceinline__ void agg3(const float* __restrict__ x, int v,
                                     long long n, long long bbase,
                                     float a[3]) {
    float dv = __ldg(&g_dinv[v]);
    float idg = dv * dv;
    long long sb = n * 3;
    a[0] = x[sb + 0] * idg;
    a[1] = x[sb + 1] * idg;
    a[2] = x[sb + 2] * idg;
    int r0 = __ldg(&g_rs[v]), r1 = __ldg(&g_rs[v + 1]);
    int i = r0;
    for (; i + 2 <= r1; i += 2) {
        int   s0 = __ldg(&g_col[i]),     s1 = __ldg(&g_col[i + 1]);
        float w0 = __ldg(&g_val[i]),     w1 = __ldg(&g_val[i + 1]);
        long long p0 = (bbase + s0) * 3, p1 = (bbase + s1) * 3;
        float x00 = x[p0], x01 = x[p0 + 1], x02 = x[p0 + 2];
        float x10 = x[p1], x11 = x[p1 + 1], x12 = x[p1 + 2];
        a[0] = fmaf(w0, x00, a[0]); a[1] = fmaf(w0, x01, a[1]); a[2] = fmaf(w0, x02, a[2]);
        a[0] = fmaf(w1, x10, a[0]); a[1] = fmaf(w1, x11, a[1]); a[2] = fmaf(w1, x12, a[2]);
    }
    if (i < r1) {
        int s = __ldg(&g_col[i]);
        float w = __ldg(&g_val[i]);
        long long p = (bbase + s) * 3;
        a[0] = fmaf(w, x[p], a[0]);
        a[1] = fmaf(w, x[p + 1], a[1]);
        a[2] = fmaf(w, x[p + 2], a[2]);
    }
}

// ==================== K1: agg3(verts) -> W1,b1,leaky -> y1 =================
__global__ void k_layer1(const float* __restrict__ verts,
                         const float* __restrict__ W1,
                         const float* __restrict__ b1,
                         float* __restrict__ y1) {
    __shared__ float sW[48], sB[16];
    if (threadIdx.x < 48) sW[threadIdx.x] = W1[threadIdx.x];
    if (threadIdx.x < 16) sB[threadIdx.x] = b1[threadIdx.x];
    __syncthreads();
    long long n = (long long)blockIdx.x * blockDim.x + threadIdx.x;
    if (n >= NN) return;
    int v = (int)(n % VN);
    long long bbase = n - v;
    float a[3];
    agg3(verts, v, n, bbase, a);
    float4* y4 = (float4*)(y1 + n * 16);
#pragma unroll
    for (int qb = 0; qb < 4; qb++) {
        float4 o;
        float* op = &o.x;
#pragma unroll
        for (int c = 0; c < 4; c++) {
            int j = qb * 4 + c;
            float t = sB[j];
            t = fmaf(a[0], sW[0 * 16 + j], t);
            t = fmaf(a[1], sW[1 * 16 + j], t);
            t = fmaf(a[2], sW[2 * 16 + j], t);
            op[c] = t > 0.0f ? t : NEG * t;
        }
        y4[qb] = o;
    }
}

// ==================== K2: agg16(y1) -> W2,b2,leaky -> *W3 -> h3 ============
__global__ void k_layer23(const float* __restrict__ y1,
                          const float* __restrict__ W2,
                          const float* __restrict__ b2,
                          const float* __restrict__ W3,
                          float* __restrict__ h3) {
    __shared__ float sW2[256], sW3[48], sB2[16];
    for (int i = threadIdx.x; i < 256; i += blockDim.x) sW2[i] = W2[i];
    if (threadIdx.x < 48) sW3[threadIdx.x] = W3[threadIdx.x];
    if (threadIdx.x < 16) sB2[threadIdx.x] = b2[threadIdx.x];
    __syncthreads();
    long long n = (long long)blockIdx.x * blockDim.x + threadIdx.x;
    if (n >= NN) return;
    int v = (int)(n % VN);
    long long bbase = n - v;
    float dv = __ldg(&g_dinv[v]);
    float idg = dv * dv;
    const float4* y4 = (const float4*)y1;
    float acc[16];
    {
        long long p = n << 2;
#pragma unroll
        for (int qb = 0; qb < 4; qb++) {
            float4 s = y4[p + qb];
            acc[qb * 4 + 0] = s.x * idg;
            acc[qb * 4 + 1] = s.y * idg;
            acc[qb * 4 + 2] = s.z * idg;
            acc[qb * 4 + 3] = s.w * idg;
        }
    }
    int r0 = __ldg(&g_rs[v]), r1 = __ldg(&g_rs[v + 1]);
    for (int i = r0; i < r1; i++) {
        int s = __ldg(&g_col[i]);
        float w = __ldg(&g_val[i]);
        long long p = (bbase + s) << 2;
        float4 q0 = y4[p + 0];
        float4 q1 = y4[p + 1];
        float4 q2 = y4[p + 2];
        float4 q3 = y4[p + 3];
        acc[0]  = fmaf(w, q0.x, acc[0]);  acc[1]  = fmaf(w, q0.y, acc[1]);
        acc[2]  = fmaf(w, q0.z, acc[2]);  acc[3]  = fmaf(w, q0.w, acc[3]);
        acc[4]  = fmaf(w, q1.x, acc[4]);  acc[5]  = fmaf(w, q1.y, acc[5]);
        acc[6]  = fmaf(w, q1.z, acc[6]);  acc[7]  = fmaf(w, q1.w, acc[7]);
        acc[8]  = fmaf(w, q2.x, acc[8]);  acc[9]  = fmaf(w, q2.y, acc[9]);
        acc[10] = fmaf(w, q2.z, acc[10]); acc[11] = fmaf(w, q2.w, acc[11]);
        acc[12] = fmaf(w, q3.x, acc[12]); acc[13] = fmaf(w, q3.y, acc[13]);
        acc[14] = fmaf(w, q3.z, acc[14]); acc[15] = fmaf(w, q3.w, acc[15]);
    }
    // epilogue: y2 = leaky(acc @ W2 + b2); h3 = y2 @ W3
    float h0 = 0.0f, h1 = 0.0f, h2 = 0.0f;
#pragma unroll
    for (int j = 0; j < 16; j++) {
        float t = sB2[j];
#pragma unroll
        for (int k = 0; k < 16; k++)
            t = fmaf(acc[k], sW2[k * 16 + j], t);
        t = t > 0.0f ? t : NEG * t;
        h0 = fmaf(t, sW3[j * 3 + 0], h0);
        h1 = fmaf(t, sW3[j * 3 + 1], h1);
        h2 = fmaf(t, sW3[j * 3 + 2], h2);
    }
    long long ob = n * 3;
    h3[ob + 0] = h0;
    h3[ob + 1] = h1;
    h3[ob + 2] = h2;
}

// ==================== K3: agg3(h3) + b3 + verts -> dout vert block =========
__global__ void k_layer3_vout(const float* __restrict__ h3,
                              const float* __restrict__ b3,
                              const float* __restrict__ verts,
                              float* __restrict__ dout) {
    long long n = (long long)blockIdx.x * blockDim.x + threadIdx.x;
    if (n >= NN) return;
    int v = (int)(n % VN);
    long long b = n / VN;
    long long bbase = n - v;
    float a[3];
    agg3(h3, v, n, bbase, a);
    long long sb = n * 3;
    long long ob = b * (VN + EN) * 3 + (long long)v * 3;
    dout[ob + 0] = verts[sb + 0] + a[0] + __ldg(&b3[0]);
    dout[ob + 1] = verts[sb + 1] + a[1] + __ldg(&b3[1]);
    dout[ob + 2] = verts[sb + 2] + a[2] + __ldg(&b3[2]);
}

// ==================== midpoints + faces ====================================
__global__ void k_mid(const int* __restrict__ edges, float* dout) {
    int t = blockIdx.x * blockDim.x + threadIdx.x;
    if (t >= BN * EN) return;
    int e = t % EN;
    int b = t / EN;
    int s = __ldg(&edges[2 * e]);
    int d = __ldg(&edges[2 * e + 1]);
    long long base = (long long)b * (VN + EN) * 3;
#pragma unroll
    for (int k = 0; k < 3; k++)
        dout[base + (long long)(VN + e) * 3 + k] =
            0.5f * (dout[base + (long long)s * 3 + k] +
                    dout[base + (long long)d * 3 + k]);
}

__global__ void k_faces4(const int* __restrict__ faces, float* __restrict__ dout,
                         int fs3) {
    int t = blockIdx.x * blockDim.x + threadIdx.x;      // quad index
    int total4 = BN * (fs3 / 4);
    if (t >= total4) return;
    int q = (t * 4) % fs3;                              // multiple of 4
    int4 f = *reinterpret_cast<const int4*>(faces + q);
    float4 o = make_float4((float)f.x, (float)f.y, (float)f.z, (float)f.w);
    reinterpret_cast<float4*>(dout + (long long)BN * (VN + EN) * 3)[t] = o;
}
__global__ void k_faces1(const int* __restrict__ faces, float* __restrict__ dout,
                         int fs3) {
    int t = blockIdx.x * blockDim.x + threadIdx.x;
    if (t >= BN * fs3) return;
    dout[(long long)BN * (VN + EN) * 3 + t] = (float)faces[t % fs3];
}

// ==================== host =================================================
static inline unsigned gdim(long long n) { return (unsigned)((n + 255) / 256); }

extern "C" void kernel_launch(void* const* d_in, const int* in_sizes, int n_in,
                              void* d_out, int out_size) {
    const float* verts = (const float*)d_in[0];
    const int*   edges = (const int*)  d_in[1];
    const int*   faces = (const int*)  d_in[2];
    const float* W1 = (const float*)d_in[3];
    const float* b1 = (const float*)d_in[4];
    const float* W2 = (const float*)d_in[5];
    const float* b2 = (const float*)d_in[6];
    const float* W3 = (const float*)d_in[7];
    const float* b3 = (const float*)d_in[8];
    int fs3 = in_sizes[2];                 // Fsub*3
    float* out = (float*)d_out;

    float *p_y1, *p_h3;
    cudaGetSymbolAddress((void**)&p_y1, g_y1);
    cudaGetSymbolAddress((void**)&p_h3, g_h3);

    const int T = 256;

    // CSR build (base graph)
    k_zero_cnt<<<gdim(VN), T>>>();
    k_count   <<<gdim(EN), T>>>(edges);
    k_scan    <<<1, 1024>>>();
    k_fill    <<<gdim(EN), T>>>(edges);

    // fused layers
    k_layer1    <<<gdim(NN), T>>>(verts, W1, b1, p_y1);
    k_layer23   <<<gdim(NN), T>>>(p_y1, W2, b2, W3, p_h3);
    k_layer3_vout<<<gdim(NN), T>>>(p_h3, b3, verts, out);

    // midpoints + faces
    k_mid<<<gdim((long long)BN * EN), T>>>(edges, out);
    if ((fs3 & 3) == 0)
        k_faces4<<<gdim((long long)BN * (fs3 / 4)), T>>>(faces, out, fs3);
    else
        k_faces1<<<gdim((long long)BN * fs3), T>>>(faces, out, fs3);
}

// round 8
// speedup vs baseline: 1.5860x; 1.0840x over previous
#include <cuda_runtime.h>
#include <cuda_fp16.h>

// SubdivideMeshes: 3x GCNConv (3->16->16->3) + leaky_relu, vertex offsets,
// edge midpoints, faces broadcast. Fixed dataset shapes:
constexpr int VN = 100000;          // vertices per mesh
constexpr int EN = 300000;          // edges per mesh
constexpr int BN = 16;              // batch
constexpr int NN = BN * VN;         // 1,600,000 batched nodes
constexpr float NEG = 0.01f;

// GCN identity: out = Ahat(xW)+b = (Ahat x)W + b. Aggregate in the NARROW dim
// per layer. y1 stored in fp16: halves the dominant round-trip and makes the
// 16-wide gather fully L2-resident (51MB < 126MB L2). Error budget: offsets
// are O(1e-4) relative to verts, fp16 noise lands ~1e-7 in the output.

// Scratch (static __device__ arrays: allocation-free per harness rules)
__device__ int    g_cnt[VN];        // in-degree counts (excl. self-loop)
__device__ int    g_rs [VN + 1];    // CSR row starts (by dst)
__device__ int    g_cur[VN];        // fill cursors
__device__ int    g_col[EN];        // CSR: src per in-edge
__device__ float  g_val[EN];        // CSR: norm per in-edge
__device__ float  g_dinv[VN];       // rsqrt(deg), deg = 1 + in-count
__device__ __half g_y1 [NN * 16];   // 51.2 MB  (layer-1 output, leaky applied)
__device__ float  g_h3 [NN * 3];    // 19.2 MB  (y2 @ W3, pre-aggregation)

// ==================== CSR build (base graph, batch-invariant) ==============
__global__ void k_zero_cnt() {
    int v = blockIdx.x * blockDim.x + threadIdx.x;
    if (v < VN) g_cnt[v] = 0;
}
__global__ void k_count(const int* __restrict__ edges) {
    int e = blockIdx.x * blockDim.x + threadIdx.x;
    if (e < EN) atomicAdd(&g_cnt[edges[2 * e + 1]], 1);
}
__global__ void k_scan() {
    __shared__ int sh[1024];
    const int T = 1024, C = (VN + T - 1) / T;
    int t = threadIdx.x;
    int beg = t * C, end = min(beg + C, VN);
    int s = 0;
    for (int i = beg; i < end; i++) s += g_cnt[i];
    sh[t] = s;
    __syncthreads();
    for (int off = 1; off < T; off <<= 1) {
        int v = (t >= off) ? sh[t - off] : 0;
        __syncthreads();
        sh[t] += v;
        __syncthreads();
    }
    int run = sh[t] - s;
    for (int i = beg; i < end; i++) {
        int c = g_cnt[i];
        g_rs[i] = run;
        g_cur[i] = run;
        g_dinv[i] = rsqrtf((float)(1 + c));
        run += c;
    }
    if (t == T - 1) g_rs[VN] = run;
}
__global__ void k_fill(const int* __restrict__ edges) {
    int e = blockIdx.x * blockDim.x + threadIdx.x;
    if (e >= EN) return;
    int s = edges[2 * e];
    int d = edges[2 * e + 1];
    int pos = atomicAdd(&g_cur[d], 1);
    g_col[pos] = s;
    g_val[pos] = g_dinv[s] * g_dinv[d];
}

// 3-dim aggregation helper (self term included).
__device__ __forceinline__ void agg3(const float* __restrict__ x, int v,
                                     long long n, long long bbase,
                                     float a[3]) {
    float dv = __ldg(&g_dinv[v]);
    float idg = dv * dv;
    long long sb = n * 3;
    a[0] = x[sb + 0] * idg;
    a[1] = x[sb + 1] * idg;
    a[2] = x[sb + 2] * idg;
    int r0 = __ldg(&g_rs[v]), r1 = __ldg(&g_rs[v + 1]);
    int i = r0;
    for (; i + 2 <= r1; i += 2) {
        int   s0 = __ldg(&g_col[i]),     s1 = __ldg(&g_col[i + 1]);
        float w0 = __ldg(&g_val[i]),     w1 = __ldg(&g_val[i + 1]);
        long long p0 = (bbase + s0) * 3, p1 = (bbase + s1) * 3;
        float x00 = x[p0], x01 = x[p0 + 1], x02 = x[p0 + 2];
        float x10 = x[p1], x11 = x[p1 + 1], x12 = x[p1 + 2];
        a[0] = fmaf(w0, x00, a[0]); a[1] = fmaf(w0, x01, a[1]); a[2] = fmaf(w0, x02, a[2]);
        a[0] = fmaf(w1, x10, a[0]); a[1] = fmaf(w1, x11, a[1]); a[2] = fmaf(w1, x12, a[2]);
    }
    if (i < r1) {
        int s = __ldg(&g_col[i]);
        float w = __ldg(&g_val[i]);
        long long p = (bbase + s) * 3;
        a[0] = fmaf(w, x[p], a[0]);
        a[1] = fmaf(w, x[p + 1], a[1]);
        a[2] = fmaf(w, x[p + 2], a[2]);
    }
}

// fma 8 halves (one uint4) into 8 float accumulators with weight w
__device__ __forceinline__ void h8_fma(uint4 u, float w, float* acc) {
    const __half2* h = (const __half2*)&u;
#pragma unroll
    for (int k = 0; k < 4; k++) {
        float2 f = __half22float2(h[k]);
        acc[2 * k + 0] = fmaf(w, f.x, acc[2 * k + 0]);
        acc[2 * k + 1] = fmaf(w, f.y, acc[2 * k + 1]);
    }
}

// ==================== K1: agg3(verts) -> W1,b1,leaky -> y1 (fp16) ==========
__global__ void k_layer1(const float* __restrict__ verts,
                         const float* __restrict__ W1,
                         const float* __restrict__ b1,
                         __half* __restrict__ y1) {
    __shared__ float sW[48], sB[16];
    if (threadIdx.x < 48) sW[threadIdx.x] = W1[threadIdx.x];
    if (threadIdx.x < 16) sB[threadIdx.x] = b1[threadIdx.x];
    __syncthreads();
    long long n = (long long)blockIdx.x * blockDim.x + threadIdx.x;
    if (n >= NN) return;
    int v = (int)(n % VN);
    long long bbase = n - v;
    float a[3];
    agg3(verts, v, n, bbase, a);
    uint4 pk[2];
    __half2* ph = (__half2*)pk;
#pragma unroll
    for (int jp = 0; jp < 8; jp++) {
        float t0 = sB[2 * jp + 0], t1 = sB[2 * jp + 1];
#pragma unroll
        for (int k = 0; k < 3; k++) {
            t0 = fmaf(a[k], sW[k * 16 + 2 * jp + 0], t0);
            t1 = fmaf(a[k], sW[k * 16 + 2 * jp + 1], t1);
        }
        t0 = t0 > 0.0f ? t0 : NEG * t0;
        t1 = t1 > 0.0f ? t1 : NEG * t1;
        ph[jp] = __float22half2_rn(make_float2(t0, t1));
    }
    uint4* y4 = (uint4*)(y1 + n * 16);
    y4[0] = pk[0];
    y4[1] = pk[1];
}

// ==================== K2: agg16(y1 fp16) -> W2,b2,leaky -> *W3 -> h3 =======
__global__ void k_layer23(const __half* __restrict__ y1,
                          const float* __restrict__ W2,
                          const float* __restrict__ b2,
                          const float* __restrict__ W3,
                          float* __restrict__ h3) {
    __shared__ float sW2[256], sW3[48], sB2[16];
    for (int i = threadIdx.x; i < 256; i += blockDim.x) sW2[i] = W2[i];
    if (threadIdx.x < 48) sW3[threadIdx.x] = W3[threadIdx.x];
    if (threadIdx.x < 16) sB2[threadIdx.x] = b2[threadIdx.x];
    __syncthreads();
    long long n = (long long)blockIdx.x * blockDim.x + threadIdx.x;
    if (n >= NN) return;
    int v = (int)(n % VN);
    long long bbase = n - v;
    float dv = __ldg(&g_dinv[v]);
    float idg = dv * dv;
    const uint4* y4 = (const uint4*)y1;   // one uint4 = 8 halves
    float acc[16];
#pragma unroll
    for (int k = 0; k < 16; k++) acc[k] = 0.0f;
    {
        long long p = n << 1;
        h8_fma(y4[p + 0], idg, acc);
        h8_fma(y4[p + 1], idg, acc + 8);
    }
    int r0 = __ldg(&g_rs[v]), r1 = __ldg(&g_rs[v + 1]);
    for (int i = r0; i < r1; i++) {
        int s = __ldg(&g_col[i]);
        float w = __ldg(&g_val[i]);
        long long p = (bbase + s) << 1;
        uint4 u0 = y4[p + 0];
        uint4 u1 = y4[p + 1];
        h8_fma(u0, w, acc);
        h8_fma(u1, w, acc + 8);
    }
    // epilogue: y2 = leaky(acc @ W2 + b2); h3 = y2 @ W3
    float h0 = 0.0f, h1 = 0.0f, h2 = 0.0f;
#pragma unroll
    for (int j = 0; j < 16; j++) {
        float t = sB2[j];
#pragma unroll
        for (int k = 0; k < 16; k++)
            t = fmaf(acc[k], sW2[k * 16 + j], t);
        t = t > 0.0f ? t : NEG * t;
        h0 = fmaf(t, sW3[j * 3 + 0], h0);
        h1 = fmaf(t, sW3[j * 3 + 1], h1);
        h2 = fmaf(t, sW3[j * 3 + 2], h2);
    }
    long long ob = n * 3;
    h3[ob + 0] = h0;
    h3[ob + 1] = h1;
    h3[ob + 2] = h2;
}

// ==================== K3: agg3(h3) + b3 + verts -> dout vert block =========
__global__ void k_layer3_vout(const float* __restrict__ h3,
                              const float* __restrict__ b3,
                              const float* __restrict__ verts,
                              float* __restrict__ dout) {
    long long n = (long long)blockIdx.x * blockDim.x + threadIdx.x;
    if (n >= NN) return;
    int v = (int)(n % VN);
    long long b = n / VN;
    long long bbase = n - v;
    float a[3];
    agg3(h3, v, n, bbase, a);
    long long sb = n * 3;
    long long ob = b * (VN + EN) * 3 + (long long)v * 3;
    dout[ob + 0] = verts[sb + 0] + a[0] + __ldg(&b3[0]);
    dout[ob + 1] = verts[sb + 1] + a[1] + __ldg(&b3[1]);
    dout[ob + 2] = verts[sb + 2] + a[2] + __ldg(&b3[2]);
}

// ==================== midpoints + faces ====================================
__global__ void k_mid(const int* __restrict__ edges, float* dout) {
    int t = blockIdx.x * blockDim.x + threadIdx.x;
    if (t >= BN * EN) return;
    int e = t % EN;
    int b = t / EN;
    int s = __ldg(&edges[2 * e]);
    int d = __ldg(&edges[2 * e + 1]);
    long long base = (long long)b * (VN + EN) * 3;
#pragma unroll
    for (int k = 0; k < 3; k++)
        dout[base + (long long)(VN + e) * 3 + k] =
            0.5f * (dout[base + (long long)s * 3 + k] +
                    dout[base + (long long)d * 3 + k]);
}

__global__ void k_faces4(const int* __restrict__ faces, float* __restrict__ dout,
                         int fs3) {
    int t = blockIdx.x * blockDim.x + threadIdx.x;      // quad index
    int total4 = BN * (fs3 / 4);
    if (t >= total4) return;
    int q = (t * 4) % fs3;                              // multiple of 4
    int4 f = *reinterpret_cast<const int4*>(faces + q);
    float4 o = make_float4((float)f.x, (float)f.y, (float)f.z, (float)f.w);
    reinterpret_cast<float4*>(dout + (long long)BN * (VN + EN) * 3)[t] = o;
}
__global__ void k_faces1(const int* __restrict__ faces, float* __restrict__ dout,
                         int fs3) {
    int t = blockIdx.x * blockDim.x + threadIdx.x;
    if (t >= BN * fs3) return;
    dout[(long long)BN * (VN + EN) * 3 + t] = (float)faces[t % fs3];
}

// ==================== host =================================================
static inline unsigned gdim(long long n) { return (unsigned)((n + 255) / 256); }

extern "C" void kernel_launch(void* const* d_in, const int* in_sizes, int n_in,
                              void* d_out, int out_size) {
    const float* verts = (const float*)d_in[0];
    const int*   edges = (const int*)  d_in[1];
    const int*   faces = (const int*)  d_in[2];
    const float* W1 = (const float*)d_in[3];
    const float* b1 = (const float*)d_in[4];
    const float* W2 = (const float*)d_in[5];
    const float* b2 = (const float*)d_in[6];
    const float* W3 = (const float*)d_in[7];
    const float* b3 = (const float*)d_in[8];
    int fs3 = in_sizes[2];                 // Fsub*3
    float* out = (float*)d_out;

    __half* p_y1;
    float*  p_h3;
    cudaGetSymbolAddress((void**)&p_y1, g_y1);
    cudaGetSymbolAddress((void**)&p_h3, g_h3);

    const int T = 256;

    // CSR build (base graph)
    k_zero_cnt<<<gdim(VN), T>>>();
    k_count   <<<gdim(EN), T>>>(edges);
    k_scan    <<<1, 1024>>>();
    k_fill    <<<gdim(EN), T>>>(edges);

    // fused layers
    k_layer1     <<<gdim(NN), T>>>(verts, W1, b1, p_y1);
    k_layer23    <<<gdim(NN), T>>>(p_y1, W2, b2, W3, p_h3);
    k_layer3_vout<<<gdim(NN), T>>>(p_h3, b3, verts, out);

    // midpoints + faces
    k_mid<<<gdim((long long)BN * EN), T>>>(edges, out);
    if ((fs3 & 3) == 0)
        k_faces4<<<gdim((long long)BN * (fs3 / 4)), T>>>(faces, out, fs3);
    else
        k_faces1<<<gdim((long long)BN * fs3), T>>>(faces, out, fs3);
}

// round 10
// speedup vs baseline: 1.7969x; 1.1330x over previous
#include <cuda_runtime.h>
#include <cuda_fp16.h>

// SubdivideMeshes: 3x GCNConv (3->16->16->3) + leaky_relu, vertex offsets,
// edge midpoints, faces broadcast. Fixed dataset shapes:
constexpr int VN = 100000;          // vertices per mesh
constexpr int EN = 300000;          // edges per mesh
constexpr int BN = 16;              // batch (power of 2, used as t&15)
constexpr long long NN = (long long)BN * VN;
constexpr float NEG = 0.01f;

// VERTEX-MAJOR intermediates: x[v][b][feat]. Thread map b = t&15, v = t>>4.
// Every neighbor gather: 16 lanes read one contiguous 192B/512B block.
// CSR metadata broadcasts across the 16 lanes sharing v.

__device__ int    g_cnt[VN];
__device__ int    g_rs [VN + 1];
__device__ int    g_cur[VN];
__device__ int    g_col[EN];
__device__ float  g_val[EN];
__device__ float  g_dinv[VN];
__device__ float  g_vt [NN * 3];    // verts, vertex-major           19.2 MB
__device__ __half g_y1 [NN * 16];   // layer-1 out (leaky applied)   51.2 MB
__device__ float  g_h3 [NN * 3];    // y2 @ W3                       19.2 MB
__device__ float  g_vf [NN * 3];    // final verts, vertex-major     19.2 MB

// ==================== CSR build (base graph, batch-invariant) ==============
__global__ void k_zero_cnt() {
    int v = blockIdx.x * blockDim.x + threadIdx.x;
    if (v < VN) g_cnt[v] = 0;
}
__global__ void k_count(const int* __restrict__ edges) {
    int e = blockIdx.x * blockDim.x + threadIdx.x;
    if (e < EN) atomicAdd(&g_cnt[edges[2 * e + 1]], 1);
}
__global__ void k_scan() {
    __shared__ int sh[1024];
    const int T = 1024, C = (VN + T - 1) / T;
    int t = threadIdx.x;
    int beg = t * C, end = min(beg + C, VN);
    int s = 0;
    for (int i = beg; i < end; i++) s += g_cnt[i];
    sh[t] = s;
    __syncthreads();
    for (int off = 1; off < T; off <<= 1) {
        int v = (t >= off) ? sh[t - off] : 0;
        __syncthreads();
        sh[t] += v;
        __syncthreads();
    }
    int run = sh[t] - s;
    for (int i = beg; i < end; i++) {
        int c = g_cnt[i];
        g_rs[i] = run;
        g_cur[i] = run;
        g_dinv[i] = rsqrtf((float)(1 + c));
        run += c;
    }
    if (t == T - 1) g_rs[VN] = run;
}
__global__ void k_fill(const int* __restrict__ edges) {
    int e = blockIdx.x * blockDim.x + threadIdx.x;
    if (e >= EN) return;
    int s = edges[2 * e];
    int d = edges[2 * e + 1];
    int pos = atomicAdd(&g_cur[d], 1);
    g_col[pos] = s;
    g_val[pos] = g_dinv[s] * g_dinv[d];
}

// ==================== transpose in: verts [B][V][3] -> vt [V][B][3] ========
// block = 768 threads handles 16 verts x 16 batches x 3. VN % 16 == 0.
__global__ void k_tin(const float* __restrict__ verts, float* __restrict__ vt) {
    __shared__ float sm[768];
    long long v0 = (long long)blockIdx.x * 16;
    int t = threadIdx.x;
    int b = t / 48, j = t % 48;
    sm[b * 48 + j] = verts[((long long)b * VN + v0) * 3 + j];   // coalesced per b
    __syncthreads();
    int vv = t / 48, r = t % 48, bb = r / 3, k = r % 3;
    vt[v0 * 48 + t] = sm[bb * 48 + vv * 3 + k];                 // coalesced out
}

// ==================== transpose out: vf [V][B][3] -> dout vert block =======
__global__ void k_tout(const float* __restrict__ vf, float* __restrict__ dout) {
    __shared__ float sm[768];
    long long v0 = (long long)blockIdx.x * 16;
    int t = threadIdx.x;
    sm[t] = vf[v0 * 48 + t];                                    // coalesced in
    __syncthreads();
    int b = t / 48, j = t % 48, vv = j / 3, k = j % 3;
    dout[(long long)b * (VN + EN) * 3 + v0 * 3 + j] = sm[vv * 48 + b * 3 + k];
}

// ==================== 3-dim aggregation, vertex-major ======================
__device__ __forceinline__ void agg3t(const float* __restrict__ x, int v, int b,
                                      float a[3]) {
    float dv = __ldg(&g_dinv[v]);
    float idg = dv * dv;
    long long self = ((long long)v * BN + b) * 3;
    a[0] = x[self + 0] * idg;
    a[1] = x[self + 1] * idg;
    a[2] = x[self + 2] * idg;
    int r0 = __ldg(&g_rs[v]), r1 = __ldg(&g_rs[v + 1]);
    int i = r0;
    for (; i + 2 <= r1; i += 2) {
        int   s0 = __ldg(&g_col[i]),   s1 = __ldg(&g_col[i + 1]);
        float w0 = __ldg(&g_val[i]),   w1 = __ldg(&g_val[i + 1]);
        long long p0 = ((long long)s0 * BN + b) * 3;
        long long p1 = ((long long)s1 * BN + b) * 3;
        float x00 = x[p0], x01 = x[p0 + 1], x02 = x[p0 + 2];
        float x10 = x[p1], x11 = x[p1 + 1], x12 = x[p1 + 2];
        a[0] = fmaf(w0, x00, a[0]); a[1] = fmaf(w0, x01, a[1]); a[2] = fmaf(w0, x02, a[2]);
        a[0] = fmaf(w1, x10, a[0]); a[1] = fmaf(w1, x11, a[1]); a[2] = fmaf(w1, x12, a[2]);
    }
    if (i < r1) {
        int s = __ldg(&g_col[i]);
        float w = __ldg(&g_val[i]);
        long long p = ((long long)s * BN + b) * 3;
        a[0] = fmaf(w, x[p], a[0]);
        a[1] = fmaf(w, x[p + 1], a[1]);
        a[2] = fmaf(w, x[p + 2], a[2]);
    }
}

// fma 8 halves (one uint4) into 8 float accumulators with weight w
__device__ __forceinline__ void h8_fma(uint4 u, float w, float* acc) {
    const __half2* h = (const __half2*)&u;
#pragma unroll
    for (int k = 0; k < 4; k++) {
        float2 f = __half22float2(h[k]);
        acc[2 * k + 0] = fmaf(w, f.x, acc[2 * k + 0]);
        acc[2 * k + 1] = fmaf(w, f.y, acc[2 * k + 1]);
    }
}

// ==================== K1: agg3(vt) -> W1,b1,leaky -> y1 (fp16, v-major) ====
__global__ void k_layer1(const float* __restrict__ vt,
                         const float* __restrict__ W1,
                         const float* __restrict__ b1,
                         __half* __restrict__ y1) {
    __shared__ float sW[48], sB[16];
    if (threadIdx.x < 48) sW[threadIdx.x] = W1[threadIdx.x];
    if (threadIdx.x < 16) sB[threadIdx.x] = b1[threadIdx.x];
    __syncthreads();
    long long t = (long long)blockIdx.x * blockDim.x + threadIdx.x;
    if (t >= NN) return;
    int b = (int)(t & 15);
    int v = (int)(t >> 4);
    float a[3];
    agg3t(vt, v, b, a);
    uint4 pk[2];
    __half2* ph = (__half2*)pk;
#pragma unroll
    for (int jp = 0; jp < 8; jp++) {
        float t0 = sB[2 * jp + 0], t1 = sB[2 * jp + 1];
#pragma unroll
        for (int k = 0; k < 3; k++) {
            t0 = fmaf(a[k], sW[k * 16 + 2 * jp + 0], t0);
            t1 = fmaf(a[k], sW[k * 16 + 2 * jp + 1], t1);
        }
        t0 = t0 > 0.0f ? t0 : NEG * t0;
        t1 = t1 > 0.0f ? t1 : NEG * t1;
        ph[jp] = __float22half2_rn(make_float2(t0, t1));
    }
    uint4* y4 = (uint4*)(y1 + t * 16);
    y4[0] = pk[0];
    y4[1] = pk[1];
}

// ==================== K2: agg16(y1) -> W2,b2,leaky -> *W3 -> h3 ============
__global__ void k_layer23(const __half* __restrict__ y1,
                          const float* __restrict__ W2,
                          const float* __restrict__ b2,
                          const float* __restrict__ W3,
                          float* __restrict__ h3) {
    __shared__ float sW2[256], sW3[48], sB2[16];
    for (int i = threadIdx.x; i < 256; i += blockDim.x) sW2[i] = W2[i];
    if (threadIdx.x < 48) sW3[threadIdx.x] = W3[threadIdx.x];
    if (threadIdx.x < 16) sB2[threadIdx.x] = b2[threadIdx.x];
    __syncthreads();
    long long t = (long long)blockIdx.x * blockDim.x + threadIdx.x;
    if (t >= NN) return;
    int b = (int)(t & 15);
    int v = (int)(t >> 4);
    float dv = __ldg(&g_dinv[v]);
    float idg = dv * dv;
    const uint4* y4 = (const uint4*)y1;   // one uint4 = 8 halves
    float acc[16];
#pragma unroll
    for (int k = 0; k < 16; k++) acc[k] = 0.0f;
    {
        long long p = t << 1;             // (v*16+b)*2
        h8_fma(y4[p + 0], idg, acc);
        h8_fma(y4[p + 1], idg, acc + 8);
    }
    int r0 = __ldg(&g_rs[v]), r1 = __ldg(&g_rs[v + 1]);
    for (int i = r0; i < r1; i++) {
        int s = __ldg(&g_col[i]);
        float w = __ldg(&g_val[i]);
        long long p = ((long long)s * BN + b) << 1;   // 16 lanes -> 512B block
        uint4 u0 = y4[p + 0];
        uint4 u1 = y4[p + 1];
        h8_fma(u0, w, acc);
        h8_fma(u1, w, acc + 8);
    }
    float h0 = 0.0f, h1 = 0.0f, h2 = 0.0f;
#pragma unroll
    for (int j = 0; j < 16; j++) {
        float x = sB2[j];
#pragma unroll
        for (int k = 0; k < 16; k++)
            x = fmaf(acc[k], sW2[k * 16 + j], x);
        x = x > 0.0f ? x : NEG * x;
        h0 = fmaf(x, sW3[j * 3 + 0], h0);
        h1 = fmaf(x, sW3[j * 3 + 1], h1);
        h2 = fmaf(x, sW3[j * 3 + 2], h2);
    }
    long long ob = t * 3;
    h3[ob + 0] = h0;
    h3[ob + 1] = h1;
    h3[ob + 2] = h2;
}

// ==================== K3: agg3(h3) + b3 + vt -> vf (vertex-major) ==========
__global__ void k_layer3(const float* __restrict__ h3,
                         const float* __restrict__ b3,
                         const float* __restrict__ vt,
                         float* __restrict__ vf) {
    long long t = (long long)blockIdx.x * blockDim.x + threadIdx.x;
    if (t >= NN) return;
    int b = (int)(t & 15);
    int v = (int)(t >> 4);
    float a[3];
    agg3t(h3, v, b, a);
    long long p = t * 3;
    vf[p + 0] = vt[p + 0] + a[0] + __ldg(&b3[0]);
    vf[p + 1] = vt[p + 1] + a[1] + __ldg(&b3[1]);
    vf[p + 2] = vt[p + 2] + a[2] + __ldg(&b3[2]);
}

// ==================== midpoints: staged via smem, all coalesced ============
// block = 512 threads handles 32 edges x 16 batches. EN % 32 == 0.
__global__ void k_mid(const int* __restrict__ edges,
                      const float* __restrict__ vf,
                      float* __restrict__ dout) {
    __shared__ float sm[32 * 48];
    int e0 = blockIdx.x * 32;
    int t = threadIdx.x;
    int b = t & 15, ei = t >> 4;
    int e = e0 + ei;
    if (e < EN) {
        int s = __ldg(&edges[2 * e]);
        int d = __ldg(&edges[2 * e + 1]);
        const float* ps = vf + ((long long)s * BN + b) * 3;   // 192B/16 lanes
        const float* pd = vf + ((long long)d * BN + b) * 3;
#pragma unroll
        for (int k = 0; k < 3; k++)
            sm[ei * 48 + b * 3 + k] = 0.5f * (ps[k] + pd[k]);
    }
    __syncthreads();
    // write: per batch, 96 contiguous floats (32 edges x 3)
    for (int o = t; o < 32 * 48; o += 512) {
        int b2 = o / 96, r = o % 96;
        int ei2 = r / 3, k2 = r % 3;
        int e2 = e0 + ei2;
        if (e2 < EN)
            dout[(long long)b2 * (VN + EN) * 3 + (long long)(VN + e0) * 3 + r]
                = sm[ei2 * 48 + b2 * 3 + k2];
    }
}

// ==================== faces ================================================
__global__ void k_faces4(const int* __restrict__ faces, float* __restrict__ dout,
                         int fs3) {
    int t = blockIdx.x * blockDim.x + threadIdx.x;
    int total4 = BN * (fs3 / 4);
    if (t >= total4) return;
    int q = (t * 4) % fs3;
    int4 f = __ldg(reinterpret_cast<const int4*>(faces + q));
    float4 o = make_float4((float)f.x, (float)f.y, (float)f.z, (float)f.w);
    reinterpret_cast<float4*>(dout + (long long)BN * (VN + EN) * 3)[t] = o;
}
__global__ void k_faces1(const int* __restrict__ faces, float* __restrict__ dout,
                         int fs3) {
    int t = blockIdx.x * blockDim.x + threadIdx.x;
    if (t >= BN * fs3) return;
    dout[(long long)BN * (VN + EN) * 3 + t] = (float)faces[t % fs3];
}

// ==================== host =================================================
static inline unsigned gdim(long long n) { return (unsigned)((n + 255) / 256); }

extern "C" void kernel_launch(void* const* d_in, const int* in_sizes, int n_in,
                              void* d_out, int out_size) {
    const float* verts = (const float*)d_in[0];
    const int*   edges = (const int*)  d_in[1];
    const int*   faces = (const int*)  d_in[2];
    const float* W1 = (const float*)d_in[3];
    const float* b1 = (const float*)d_in[4];
    const float* W2 = (const float*)d_in[5];
    const float* b2 = (const float*)d_in[6];
    const float* W3 = (const float*)d_in[7];
    const float* b3 = (const float*)d_in[8];
    int fs3 = in_sizes[2];
    float* out = (float*)d_out;

    float *p_vt, *p_h3, *p_vf;
    __half* p_y1;
    cudaGetSymbolAddress((void**)&p_vt, g_vt);
    cudaGetSymbolAddress((void**)&p_y1, g_y1);
    cudaGetSymbolAddress((void**)&p_h3, g_h3);
    cudaGetSymbolAddress((void**)&p_vf, g_vf);

    const int T = 256;

    // CSR build (base graph) + input transpose
    k_zero_cnt<<<gdim(VN), T>>>();
    k_count   <<<gdim(EN), T>>>(edges);
    k_scan    <<<1, 1024>>>();
    k_fill    <<<gdim(EN), T>>>(edges);
    k_tin     <<<VN / 16, 768>>>(verts, p_vt);

    // fused layers (vertex-major)
    k_layer1 <<<gdim(NN), T>>>(p_vt, W1, b1, p_y1);
    k_layer23<<<gdim(NN), T>>>(p_y1, W2, b2, W3, p_h3);
    k_layer3 <<<gdim(NN), T>>>(p_h3, b3, p_vt, p_vf);

    // outputs
    k_tout<<<VN / 16, 768>>>(p_vf, out);
    k_mid <<<(EN + 31) / 32, 512>>>(edges, p_vf, out);
    if ((fs3 & 3) == 0)
        k_faces4<<<gdim((long long)BN * (fs3 / 4)), T>>>(faces, out, fs3);
    else
        k_faces1<<<gdim((long long)BN * fs3), T>>>(faces, out, fs3);
}

// round 16
// speedup vs baseline: 2.0096x; 1.1184x over previous
#include <cuda_runtime.h>
#include <cuda_fp16.h>

// SubdivideMeshes: 3x GCNConv (3->16->16->3) + leaky_relu, vertex offsets,
// edge midpoints, faces broadcast. Fixed dataset shapes:
constexpr int VN = 100000;          // vertices per mesh
constexpr int EN = 300000;          // edges per mesh
constexpr int BN = 16;              // batch
constexpr long long NN = (long long)BN * VN;
constexpr float NEG = 0.01f;

// VERTEX-MAJOR intermediates x[v][b][feat]; layer kernels process 2 batches
// (b, b+8) per thread for 2x memory-level parallelism in the neighbor loops.

__device__ int    g_cnt[VN];
__device__ int    g_rs [VN + 1];
__device__ int    g_cur[VN];
__device__ int    g_col[EN];
__device__ float  g_val[EN];
__device__ float  g_dinv[VN];
__device__ float  g_vt [NN * 3];    // verts, vertex-major           19.2 MB
__device__ __half g_y1 [NN * 16];   // layer-1 out (leaky applied)   51.2 MB
__device__ float  g_h3 [NN * 3];    // y2 @ W3                       19.2 MB
__device__ float  g_vf [NN * 3];    // final verts, vertex-major     19.2 MB

// ==================== CSR build (base graph, batch-invariant) ==============
__global__ void k_count(const int* __restrict__ edges) {
    int e = blockIdx.x * blockDim.x + threadIdx.x;
    if (e < EN) atomicAdd(&g_cnt[edges[2 * e + 1]], 1);
}
__global__ void k_scan() {
    __shared__ int sh[1024];
    const int T = 1024, C = (VN + T - 1) / T;
    int t = threadIdx.x;
    int beg = t * C, end = min(beg + C, VN);
    int s = 0;
    for (int i = beg; i < end; i++) s += g_cnt[i];
    sh[t] = s;
    __syncthreads();
    for (int off = 1; off < T; off <<= 1) {
        int v = (t >= off) ? sh[t - off] : 0;
        __syncthreads();
        sh[t] += v;
        __syncthreads();
    }
    int run = sh[t] - s;
    for (int i = beg; i < end; i++) {
        int c = g_cnt[i];
        g_rs[i] = run;
        g_cur[i] = run;
        g_dinv[i] = rsqrtf((float)(1 + c));
        run += c;
    }
    if (t == T - 1) g_rs[VN] = run;
}
__global__ void k_fill(const int* __restrict__ edges) {
    int e = blockIdx.x * blockDim.x + threadIdx.x;
    if (e >= EN) return;
    int s = edges[2 * e];
    int d = edges[2 * e + 1];
    int pos = atomicAdd(&g_cur[d], 1);
    g_col[pos] = s;
    g_val[pos] = g_dinv[s] * g_dinv[d];
}

// ==================== transpose in: verts [B][V][3] -> vt [V][B][3] ========
__global__ void k_tin(const float* __restrict__ verts, float* __restrict__ vt) {
    __shared__ float sm[768];
    long long v0 = (long long)blockIdx.x * 16;
    int t = threadIdx.x;
    int b = t / 48, j = t % 48;
    sm[b * 48 + j] = verts[((long long)b * VN + v0) * 3 + j];
    __syncthreads();
    int vv = t / 48, r = t % 48, bb = r / 3, k = r % 3;
    vt[v0 * 48 + t] = sm[bb * 48 + vv * 3 + k];
}

// fma 8 halves (one uint4) into 8 float accumulators with weight w
__device__ __forceinline__ void h8_fma(uint4 u, float w, float* acc) {
    const __half2* h = (const __half2*)&u;
#pragma unroll
    for (int k = 0; k < 4; k++) {
        float2 f = __half22float2(h[k]);
        acc[2 * k + 0] = fmaf(w, f.x, acc[2 * k + 0]);
        acc[2 * k + 1] = fmaf(w, f.y, acc[2 * k + 1]);
    }
}

// ==================== K1: agg3(vt) x2 batches -> W1,b1,leaky -> y1 =========
// thread u handles (v, b) and (v, b+8); b = u&7, v = u>>3.
__global__ void k_layer1(const float* __restrict__ vt,
                         const float* __restrict__ W1,
                         const float* __restrict__ b1,
                         __half* __restrict__ y1) {
    __shared__ float sW[48], sB[16];
    if (threadIdx.x < 48) sW[threadIdx.x] = W1[threadIdx.x];
    if (threadIdx.x < 16) sB[threadIdx.x] = b1[threadIdx.x];
    __syncthreads();
    long long u = (long long)blockIdx.x * blockDim.x + threadIdx.x;
    if (u >= NN / 2) return;
    int b = (int)(u & 7);
    int v = (int)(u >> 3);
    float dvv = __ldg(&g_dinv[v]);
    float idg = dvv * dvv;
    float a0[3], a1[3];
    {
        long long p0 = ((long long)v * BN + b) * 3;
        long long p1 = p0 + 24;                 // (b+8)*3
        float s00 = vt[p0], s01 = vt[p0 + 1], s02 = vt[p0 + 2];
        float s10 = vt[p1], s11 = vt[p1 + 1], s12 = vt[p1 + 2];
        a0[0] = s00 * idg; a0[1] = s01 * idg; a0[2] = s02 * idg;
        a1[0] = s10 * idg; a1[1] = s11 * idg; a1[2] = s12 * idg;
    }
    int r0 = __ldg(&g_rs[v]), r1 = __ldg(&g_rs[v + 1]);
    for (int i = r0; i < r1; i++) {
        int s = __ldg(&g_col[i]);
        float w = __ldg(&g_val[i]);
        long long p0 = ((long long)s * BN + b) * 3;
        long long p1 = p0 + 24;
        float x00 = vt[p0], x01 = vt[p0 + 1], x02 = vt[p0 + 2];
        float x10 = vt[p1], x11 = vt[p1 + 1], x12 = vt[p1 + 2];
        a0[0] = fmaf(w, x00, a0[0]); a0[1] = fmaf(w, x01, a0[1]); a0[2] = fmaf(w, x02, a0[2]);
        a1[0] = fmaf(w, x10, a1[0]); a1[1] = fmaf(w, x11, a1[1]); a1[2] = fmaf(w, x12, a1[2]);
    }
    uint4 pk[4];
    __half2* ph = (__half2*)pk;
#pragma unroll
    for (int half_ix = 0; half_ix < 2; half_ix++) {
        const float* a = half_ix ? a1 : a0;
#pragma unroll
        for (int jp = 0; jp < 8; jp++) {
            float t0 = sB[2 * jp + 0], t1 = sB[2 * jp + 1];
#pragma unroll
            for (int k = 0; k < 3; k++) {
                t0 = fmaf(a[k], sW[k * 16 + 2 * jp + 0], t0);
                t1 = fmaf(a[k], sW[k * 16 + 2 * jp + 1], t1);
            }
            t0 = t0 > 0.0f ? t0 : NEG * t0;
            t1 = t1 > 0.0f ? t1 : NEG * t1;
            ph[half_ix * 8 + jp] = __float22half2_rn(make_float2(t0, t1));
        }
    }
    uint4* y4 = (uint4*)y1;
    long long q0 = ((long long)v * BN + b) << 1;
    y4[q0 + 0]  = pk[0];
    y4[q0 + 1]  = pk[1];
    y4[q0 + 16] = pk[2];   // (b+8) slot
    y4[q0 + 17] = pk[3];
}

// ==================== K2: agg16 x2 batches -> W2,b2,leaky -> *W3 -> h3 =====
__global__ void k_layer23(const __half* __restrict__ y1,
                          const float* __restrict__ W2,
                          const float* __restrict__ b2,
                          const float* __restrict__ W3,
                          float* __restrict__ h3) {
    __shared__ float sW2[256], sW3[48], sB2[16];
    for (int i = threadIdx.x; i < 256; i += blockDim.x) sW2[i] = W2[i];
    if (threadIdx.x < 48) sW3[threadIdx.x] = W3[threadIdx.x];
    if (threadIdx.x < 16) sB2[threadIdx.x] = b2[threadIdx.x];
    __syncthreads();
    long long u = (long long)blockIdx.x * blockDim.x + threadIdx.x;
    if (u >= NN / 2) return;
    int b = (int)(u & 7);
    int v = (int)(u >> 3);
    float dvv = __ldg(&g_dinv[v]);
    float idg = dvv * dvv;
    const uint4* y4 = (const uint4*)y1;
    float acc0[16], acc1[16];
    {
        long long p = ((long long)v * BN + b) << 1;
        uint4 u0 = y4[p], u1 = y4[p + 1], u2 = y4[p + 16], u3 = y4[p + 17];
#pragma unroll
        for (int k = 0; k < 16; k++) { acc0[k] = 0.0f; acc1[k] = 0.0f; }
        h8_fma(u0, idg, acc0); h8_fma(u1, idg, acc0 + 8);
        h8_fma(u2, idg, acc1); h8_fma(u3, idg, acc1 + 8);
    }
    int r0 = __ldg(&g_rs[v]), r1 = __ldg(&g_rs[v + 1]);
    for (int i = r0; i < r1; i++) {
        int s = __ldg(&g_col[i]);
        float w = __ldg(&g_val[i]);
        long long p = ((long long)s * BN + b) << 1;
        uint4 u0 = y4[p];          // 4 independent loads in flight
        uint4 u1 = y4[p + 1];
        uint4 u2 = y4[p + 16];
        uint4 u3 = y4[p + 17];
        h8_fma(u0, w, acc0); h8_fma(u1, w, acc0 + 8);
        h8_fma(u2, w, acc1); h8_fma(u3, w, acc1 + 8);
    }
    long long ob0 = ((long long)v * BN + b) * 3;
#pragma unroll
    for (int half_ix = 0; half_ix < 2; half_ix++) {
        const float* acc = half_ix ? acc1 : acc0;
        float h0 = 0.0f, h1 = 0.0f, h2 = 0.0f;
#pragma unroll
        for (int j = 0; j < 16; j++) {
            float x = sB2[j];
#pragma unroll
            for (int k = 0; k < 16; k++)
                x = fmaf(acc[k], sW2[k * 16 + j], x);
            x = x > 0.0f ? x : NEG * x;
            h0 = fmaf(x, sW3[j * 3 + 0], h0);
            h1 = fmaf(x, sW3[j * 3 + 1], h1);
            h2 = fmaf(x, sW3[j * 3 + 2], h2);
        }
        long long ob = ob0 + half_ix * 24;
        h3[ob + 0] = h0;
        h3[ob + 1] = h1;
        h3[ob + 2] = h2;
    }
}

// ==================== K3: agg3(h3)+b3+vt -> vf AND transposed dout =========
// block = 256 threads = 16 vertices x 16 batches; fuses the output transpose.
__global__ void k_layer3_out(const float* __restrict__ h3,
                             const float* __restrict__ b3,
                             const float* __restrict__ vt,
                             float* __restrict__ vf,
                             float* __restrict__ dout) {
    __shared__ float sm[768];
    int t = threadIdx.x;
    long long v0 = (long long)blockIdx.x * 16;
    int b = t & 15;
    int v = (int)v0 + (t >> 4);
    float dvv = __ldg(&g_dinv[v]);
    float idg = dvv * dvv;
    long long self = ((long long)v * BN + b) * 3;
    float a0 = h3[self + 0] * idg;
    float a1 = h3[self + 1] * idg;
    float a2 = h3[self + 2] * idg;
    int r0 = __ldg(&g_rs[v]), r1 = __ldg(&g_rs[v + 1]);
    for (int i = r0; i < r1; i++) {
        int s = __ldg(&g_col[i]);
        float w = __ldg(&g_val[i]);
        long long p = ((long long)s * BN + b) * 3;
        a0 = fmaf(w, h3[p], a0);
        a1 = fmaf(w, h3[p + 1], a1);
        a2 = fmaf(w, h3[p + 2], a2);
    }
    a0 += vt[self + 0] + __ldg(&b3[0]);
    a1 += vt[self + 1] + __ldg(&b3[1]);
    a2 += vt[self + 2] + __ldg(&b3[2]);
    vf[self + 0] = a0;             // vertex-major (for k_mid), coalesced
    vf[self + 1] = a1;
    vf[self + 2] = a2;
    int vv = t >> 4;
    sm[vv * 48 + b * 3 + 0] = a0;
    sm[vv * 48 + b * 3 + 1] = a1;
    sm[vv * 48 + b * 3 + 2] = a2;
    __syncthreads();
    // transposed write: per batch, 48 contiguous floats at dout[b][(v0..v0+15)][3]
    for (int o = t; o < 768; o += 256) {
        int b2 = o / 48, j = o % 48;
        dout[(long long)b2 * (VN + EN) * 3 + v0 * 3 + j]
            = sm[(j / 3) * 48 + b2 * 3 + (j % 3)];
    }
}

// ==================== midpoints: staged via smem, all coalesced ============
__global__ void k_mid(const int* __restrict__ edges,
                      const float* __restrict__ vf,
                      float* __restrict__ dout) {
    __shared__ float sm[32 * 48];
    int e0 = blockIdx.x * 32;
    int t = threadIdx.x;
    int b = t & 15, ei = t >> 4;
    int e = e0 + ei;
    if (e < EN) {
        int s = __ldg(&edges[2 * e]);
        int d = __ldg(&edges[2 * e + 1]);
        const float* ps = vf + ((long long)s * BN + b) * 3;
        const float* pd = vf + ((long long)d * BN + b) * 3;
#pragma unroll
        for (int k = 0; k < 3; k++)
            sm[ei * 48 + b * 3 + k] = 0.5f * (ps[k] + pd[k]);
    }
    __syncthreads();
    for (int o = t; o < 32 * 48; o += 512) {
        int b2 = o / 96, r = o % 96;
        int ei2 = r / 3, k2 = r % 3;
        int e2 = e0 + ei2;
        if (e2 < EN)
            dout[(long long)b2 * (VN + EN) * 3 + (long long)(VN + e0) * 3 + r]
                = sm[ei2 * 48 + b2 * 3 + k2];
    }
}

// ==================== faces ================================================
__global__ void k_faces4(const int* __restrict__ faces, float* __restrict__ dout,
                         int fs3) {
    int t = blockIdx.x * blockDim.x + threadIdx.x;
    int total4 = BN * (fs3 / 4);
    if (t >= total4) return;
    int q = (t * 4) % fs3;
    int4 f = __ldg(reinterpret_cast<const int4*>(faces + q));
    float4 o = make_float4((float)f.x, (float)f.y, (float)f.z, (float)f.w);
    reinterpret_cast<float4*>(dout + (long long)BN * (VN + EN) * 3)[t] = o;
}
__global__ void k_faces1(const int* __restrict__ faces, float* __restrict__ dout,
                         int fs3) {
    int t = blockIdx.x * blockDim.x + threadIdx.x;
    if (t >= BN * fs3) return;
    dout[(long long)BN * (VN + EN) * 3 + t] = (float)faces[t % fs3];
}

// ==================== host =================================================
static inline unsigned gdim(long long n) { return (unsigned)((n + 255) / 256); }

extern "C" void kernel_launch(void* const* d_in, const int* in_sizes, int n_in,
                              void* d_out, int out_size) {
    const float* verts = (const float*)d_in[0];
    const int*   edges = (const int*)  d_in[1];
    const int*   faces = (const int*)  d_in[2];
    const float* W1 = (const float*)d_in[3];
    const float* b1 = (const float*)d_in[4];
    const float* W2 = (const float*)d_in[5];
    const float* b2 = (const float*)d_in[6];
    const float* W3 = (const float*)d_in[7];
    const float* b3 = (const float*)d_in[8];
    int fs3 = in_sizes[2];
    float* out = (float*)d_out;

    float *p_vt, *p_h3, *p_vf;
    __half* p_y1;
    int* p_cnt;
    cudaGetSymbolAddress((void**)&p_vt,  g_vt);
    cudaGetSymbolAddress((void**)&p_y1,  g_y1);
    cudaGetSymbolAddress((void**)&p_h3,  g_h3);
    cudaGetSymbolAddress((void**)&p_vf,  g_vf);
    cudaGetSymbolAddress((void**)&p_cnt, g_cnt);

    const int T = 256;

    // CSR build (base graph) + input transpose
    cudaMemsetAsync(p_cnt, 0, VN * sizeof(int));
    k_count<<<gdim(EN), T>>>(edges);
    k_scan <<<1, 1024>>>();
    k_fill <<<gdim(EN), T>>>(edges);
    k_tin  <<<VN / 16, 768>>>(verts, p_vt);

    // fused layers (vertex-major; layer1/23 process 2 batches per thread)
    k_layer1    <<<gdim(NN / 2), T>>>(p_vt, W1, b1, p_y1);
    k_layer23   <<<gdim(NN / 2), T>>>(p_y1, W2, b2, W3, p_h3);
    k_layer3_out<<<VN / 16, 256>>>(p_h3, b3, p_vt, p_vf, out);

    // midpoints + faces
    k_mid<<<(EN + 31) / 32, 512>>>(edges, p_vf, out);
    if ((fs3 & 3) == 0)
        k_faces4<<<gdim((long long)BN * (fs3 / 4)), T>>>(faces, out, fs3);
    else
        k_faces1<<<gdim((long long)BN * fs3), T>>>(faces, out, fs3);
}